// round 15
// baseline (speedup 1.0000x reference)
#include <cuda_runtime.h>
#include <cuda_fp16.h>
#include <cstdint>

// ---------------------------------------------------------------------------
// GAT 3-layer forward, fp16 feature path (fp32 attention math).
// hist: 3 block ranges — degree histogram+rank | fp32->fp16 feat convert |
//       one-time WT/al/ar staging.
// GEMM: mma.sync m16n8k16, multi-tile blocks (WT staged once), all global
//       accesses 16B-coalesced, fused el/er epilogue.
// CSR: warp-shfl scan (self-zeroing) | vectorized atomic-free scatter.
// agg: single-pass warp-per-dst softmax+aggregate.
// ---------------------------------------------------------------------------

#define NMAX 50000
#define NPMAX 50048          // multiple of 128
#define EMAX 800000
#define NBMAX 64

// WT layout (halfs): layer1 [0,13312) SP=104, layer2 [13312,20992) SP=120,
// layer3 [20992,23296) SP=72. al/ar tables: 128+64+32 = 224 floats.
#define WOFF1 0
#define WOFF2 13312
#define WOFF3 20992
#define WTOT  23296
#define AOFF1 0
#define AOFF2 128
#define AOFF3 192
#define ATOT  224

__device__ __align__(16) __half g_xh1[NPMAX * 96];        // fp16 feat (converted)
__device__ __align__(16) unsigned char g_h[NPMAX * 256];  // hbuf half rows HP=H*32
__device__ __align__(16) __half g_xh2[NPMAX * 112];       // agg1 out (L2 input)
__device__ __align__(16) __half g_xh3[NPMAX * 64];        // agg2 out (L3 input)
__device__ __align__(16) float g_el[NPMAX * 4];
__device__ __align__(16) float g_er[NPMAX * 4];
__device__ __align__(16) __half g_wt[WTOT];               // zero-init; pads stay 0
__device__ __align__(16) float g_alx[ATOT];
__device__ __align__(16) float g_arx[ATOT];
__device__ int   g_cnt[NMAX];    // ZERO at entry (load-init; re-zeroed by scan1)
__device__ int   g_rank[EMAX];
__device__ int   g_loc[NMAX];
__device__ int   g_bsum[NBMAX];
__device__ int   g_ssrc[EMAX];
__device__ int   g_done;         // ZERO at entry (reset by last scan1 block)

// ---------------------------------------------------------------------------
__device__ __forceinline__ void mma16816(float c[4], uint32_t a0, uint32_t a1,
                                         uint32_t a2, uint32_t a3,
                                         uint32_t b0, uint32_t b1) {
    asm volatile(
        "mma.sync.aligned.m16n8k16.row.col.f32.f16.f16.f32 "
        "{%0,%1,%2,%3}, {%4,%5,%6,%7}, {%8,%9}, {%0,%1,%2,%3};"
        : "+f"(c[0]), "+f"(c[1]), "+f"(c[2]), "+f"(c[3])
        : "r"(a0), "r"(a1), "r"(a2), "r"(a3), "r"(b0), "r"(b1));
}

__device__ __forceinline__ void ldsm_x4(uint32_t& r0, uint32_t& r1,
                                        uint32_t& r2, uint32_t& r3, uint32_t addr) {
    asm volatile("ldmatrix.sync.aligned.m8n8.x4.shared.b16 {%0,%1,%2,%3}, [%4];"
                 : "=r"(r0), "=r"(r1), "=r"(r2), "=r"(r3) : "r"(addr));
}

// ---------------------------------------------------------------------------
// hist: block ranges: [0,hb) degree histogram + rank (vectorized),
// [hb,hb+pb) fp32->fp16 feature convert (output-indexed, coalesced stores),
// [hb+pb,hb+pb+8) one-time WT/al/ar staging. cnt zero at entry.
__global__ void hist_kernel(const int* __restrict__ dst, int* cnt, int* rank, int e,
                            int hb, int pb,
                            const float* __restrict__ feat, __half* __restrict__ xh,
                            int n, int np,
                            const float* __restrict__ W1, const float* __restrict__ al1,
                            const float* __restrict__ ar1,
                            const float* __restrict__ W2, const float* __restrict__ al2,
                            const float* __restrict__ ar2,
                            const float* __restrict__ W3, const float* __restrict__ al3,
                            const float* __restrict__ ar3) {
    int tid = threadIdx.x;
    int bx = (int)blockIdx.x;
    if (bx < hb) {
        int i = (bx * 256 + tid) * 4;
        if (i + 3 < e) {
            int4 d4 = *(const int4*)(dst + i);
            int4 r4;
            r4.x = atomicAdd(&cnt[d4.x], 1);
            r4.y = atomicAdd(&cnt[d4.y], 1);
            r4.z = atomicAdd(&cnt[d4.z], 1);
            r4.w = atomicAdd(&cnt[d4.w], 1);
            *(int4*)(rank + i) = r4;
        } else {
            for (int j = i; j < e; j++) rank[j] = atomicAdd(&cnt[dst[j]], 1);
        }
        return;
    }
    if (bx < hb + pb) {
        int i = (bx - hb) * 256 + tid;       // output-indexed (padded layout)
        if (i < np * 96) {
            int node = i / 96, k = i - node * 96;
            float v = (node < n && k < 93) ? feat[node * 93 + k] : 0.f;
            xh[i] = __float2half_rn(v);
        }
        return;
    }
    int b = bx - hb - pb;                    // 0..7 staging blocks
    for (int idx = b * 256 + tid; idx < WTOT; idx += 8 * 256) {
        float v = 0.f;
        int loc, sp, kr, col, k, d, h;
        if (idx < WOFF2) {
            loc = idx - WOFF1; sp = 104; kr = 93;
            col = loc / sp; k = loc - col * sp; d = col & 31; h = col >> 5;
            if (k < kr && d < 25) v = W1[k * 100 + h * 25 + d];
        } else if (idx < WOFF3) {
            loc = idx - WOFF2; sp = 120; kr = 100;
            col = loc / sp; k = loc - col * sp; d = col & 31; h = col >> 5;
            if (k < kr && d < 25) v = W2[k * 50 + h * 25 + d];
        } else {
            loc = idx - WOFF3; sp = 72; kr = 50;
            col = loc / sp; k = loc - col * sp; d = col & 31;
            if (k < kr && d < 25) v = W3[k * 25 + d];
        }
        g_wt[idx] = __float2half_rn(v);
    }
    for (int idx = b * 256 + tid; idx < ATOT; idx += 8 * 256) {
        int d = idx & 31;
        float va = 0.f, vr = 0.f;
        if (idx < AOFF2) {
            int h = idx >> 5;
            if (d < 25) { va = al1[h * 25 + d]; vr = ar1[h * 25 + d]; }
        } else if (idx < AOFF3) {
            int h = (idx - AOFF2) >> 5;
            if (d < 25) { va = al2[h * 25 + d]; vr = ar2[h * 25 + d]; }
        } else {
            if (d < 25) { va = al3[d]; vr = ar3[d]; }
        }
        g_alx[idx] = va;
        g_arx[idx] = vr;
    }
}

// per-chunk exclusive scan (warp-shfl) + fused cross-chunk scan; re-zeros cnt/done.
__global__ void scan1_kernel(int* cnt, int* loc, int* bsum,
                             int* done, int n, int nb) {
    __shared__ int wsum[32];
    __shared__ int last;
    int tid = threadIdx.x;
    int lane = tid & 31, wid = tid >> 5;
    int i = blockIdx.x * 1024 + tid;
    int v = (i < n) ? cnt[i] : 0;
    if (i < n) cnt[i] = 0;                 // restore zero invariant

    int x = v;
#pragma unroll
    for (int o = 1; o < 32; o <<= 1) {
        int t = __shfl_up_sync(0xffffffffu, x, o);
        if (lane >= o) x += t;
    }
    if (lane == 31) wsum[wid] = x;
    __syncthreads();
    if (wid == 0) {
        int y = wsum[lane];
        int z = y;
#pragma unroll
        for (int o = 1; o < 32; o <<= 1) {
            int t = __shfl_up_sync(0xffffffffu, z, o);
            if (lane >= o) z += t;
        }
        wsum[lane] = z - y;                // exclusive warp base
    }
    __syncthreads();
    int incl = x + wsum[wid];
    if (i < n) loc[i] = incl - v;
    if (tid == 1023) bsum[blockIdx.x] = incl;
    __threadfence();
    __syncthreads();
    if (tid == 0) last = (atomicAdd(done, 1) == gridDim.x - 1);
    __syncthreads();
    if (last) {
        if (tid < 32) {
            int a = (tid < nb) ? bsum[tid] : 0;
            int b = (tid + 32 < nb) ? bsum[tid + 32] : 0;
            int ai = a, bi = b;
#pragma unroll
            for (int o = 1; o < 32; o <<= 1) {
                int t = __shfl_up_sync(0xffffffffu, ai, o);
                if (tid >= o) ai += t;
            }
            int tot = __shfl_sync(0xffffffffu, ai, 31);
#pragma unroll
            for (int o = 1; o < 32; o <<= 1) {
                int t = __shfl_up_sync(0xffffffffu, bi, o);
                if (tid >= o) bi += t;
            }
            if (tid < nb) bsum[tid] = ai - a;
            if (tid + 32 < nb) bsum[tid + 32] = bi - b + tot;
        }
        if (tid == 0) *done = 0;           // restore zero invariant
    }
}

// vectorized atomic-free scatter: p = loc[d] + bsum[chunk] + rank[i]
__global__ void scatter_kernel(const int* __restrict__ src, const int* __restrict__ dst,
                               const int* __restrict__ loc, const int* __restrict__ bsum,
                               const int* __restrict__ rank, int* ssrc, int e) {
    int i = (blockIdx.x * blockDim.x + threadIdx.x) * 4;
    if (i + 3 < e) {
        int4 d4 = *(const int4*)(dst + i);
        int4 s4 = *(const int4*)(src + i);
        int4 r4 = *(const int4*)(rank + i);
        ssrc[loc[d4.x] + bsum[d4.x >> 10] + r4.x] = s4.x;
        ssrc[loc[d4.y] + bsum[d4.y >> 10] + r4.y] = s4.y;
        ssrc[loc[d4.z] + bsum[d4.z >> 10] + r4.z] = s4.z;
        ssrc[loc[d4.w] + bsum[d4.w >> 10] + r4.w] = s4.w;
    } else {
        for (int j = i; j < e; j++) {
            int d = dst[j];
            ssrc[loc[d] + bsum[d >> 10] + rank[j]] = src[j];
        }
    }
}

// ---------------------------------------------------------------------------
// fp16 tensor-core GEMM, multi-tile blocks (WT staged once per block).
// x fp16 [NP, KP] zero tails. 256 threads / 8 warps; WSPLIT warps co-own each
// 16-row tile (disjoint heads). All global accesses 16B-coalesced.
template <int KP, int H, int WSPLIT, int WOFF, int AOFF>
__global__ void __launch_bounds__(256)
gemm_mma_kernel(const __half* __restrict__ x,
                __half* __restrict__ hbuf,
                float* __restrict__ el, float* __restrict__ er,
                int ntiles) {
    const int MT = H * 4;
    const int NTH = MT / WSPLIT;           // n-tiles per warp
    const int TILES = 8 / WSPLIT;
    const int ROWS = TILES * 16;
    const int SP  = KP + 8;                // WT / x-tile stride (halfs)
    const int HP  = H * 32;
    const int SST = HP + 8;                // store-tile stride
    const int XW  = (SP > SST) ? SP : SST;
    __shared__ __align__(16) __half WT[HP * SP];
    __shared__ __align__(16) __half XB[ROWS * XW];   // x-tile, then store-tile

    int tid = threadIdx.x;
    // stage WT once (linear 16B copy)
    const __half* wtg = g_wt + WOFF;
    for (int idx = tid * 8; idx < HP * SP; idx += 256 * 8)
        *(uint4*)(WT + idx) = *(const uint4*)(wtg + idx);

    int wid = tid >> 5, lane = tid & 31;
    int g4 = lane >> 2, t4 = lane & 3;
    int t = wid / WSPLIT;
    int ntbase = (wid % WSPLIT) * NTH;     // multiple of 4
    const int HL = NTH / 4;
    const int hbase = ntbase / 4;

    int lm_row = lane & 7, sel = lane >> 3;
    int lm_nt = sel >> 1, lm_k = (sel & 1) * 8;
    uint32_t wt_u32 = (uint32_t)__cvta_generic_to_shared(WT)
        + (uint32_t)((((ntbase + lm_nt) * 8 + lm_row) * SP + lm_k) * 2);
    uint32_t xa_u32 = (uint32_t)__cvta_generic_to_shared(XB)
        + (uint32_t)(((t * 16 + (lane & 15)) * SP + (lane >> 4) * 8) * 2);

    const float* alxg = g_alx + AOFF;
    const float* arxg = g_arx + AOFF;

    for (int tile = blockIdx.x; tile < ntiles; tile += gridDim.x) {
        __syncthreads();   // XB free (prev output copy done) + WT ready (iter 0)
        // ---- stage x-tile (coalesced LDG.128) ----
        {
            const __half* xg = x + (size_t)tile * ROWS * KP;
            const int CRX = KP / 8;
            for (int u = tid; u < ROWS * CRX; u += 256) {
                int row = u / CRX, c = u - row * CRX;
                *(uint4*)(XB + row * SP + c * 8) =
                    *(const uint4*)(xg + row * KP + c * 8);
            }
        }
        __syncthreads();

        // ---- mainloop ----
        float c[NTH][4];
#pragma unroll
        for (int nt = 0; nt < NTH; nt++)
#pragma unroll
            for (int q = 0; q < 4; q++) c[nt][q] = 0.f;

#pragma unroll
        for (int ks = 0; ks < KP / 16; ks++) {
            uint32_t a0, a1, a2, a3;
            ldsm_x4(a0, a1, a2, a3, xa_u32 + (uint32_t)(ks * 32));
#pragma unroll
            for (int ntp = 0; ntp < NTH / 2; ntp++) {
                uint32_t b00, b01, b10, b11;
                uint32_t addr = wt_u32 + (uint32_t)((ntp * 16 * SP + ks * 16) * 2);
                ldsm_x4(b00, b01, b10, b11, addr);
                mma16816(c[2 * ntp], a0, a1, a2, a3, b00, b01);
                mma16816(c[2 * ntp + 1], a0, a1, a2, a3, b10, b11);
            }
        }

        // ---- el/er epilogue ----
        int m0 = tile * ROWS + t * 16;
        float el0[HL], er0[HL], el8[HL], er8[HL];
#pragma unroll
        for (int h = 0; h < HL; h++) { el0[h] = er0[h] = el8[h] = er8[h] = 0.f; }
#pragma unroll
        for (int nt = 0; nt < NTH; nt++) {
            int col = (ntbase + nt) * 8 + t4 * 2;
            int h = nt >> 2;
            float2 av = *(const float2*)&alxg[col];
            float2 rv = *(const float2*)&arxg[col];
            el0[h] += c[nt][0] * av.x + c[nt][1] * av.y;
            er0[h] += c[nt][0] * rv.x + c[nt][1] * rv.y;
            el8[h] += c[nt][2] * av.x + c[nt][3] * av.y;
            er8[h] += c[nt][2] * rv.x + c[nt][3] * rv.y;
        }
#pragma unroll
        for (int h = 0; h < HL; h++) {
#pragma unroll
            for (int o = 1; o <= 2; o <<= 1) {
                el0[h] += __shfl_xor_sync(0xffffffffu, el0[h], o);
                er0[h] += __shfl_xor_sync(0xffffffffu, er0[h], o);
                el8[h] += __shfl_xor_sync(0xffffffffu, el8[h], o);
                er8[h] += __shfl_xor_sync(0xffffffffu, er8[h], o);
            }
        }
        if (t4 == 0) {
            int n0 = m0 + g4;
#pragma unroll
            for (int h = 0; h < HL; h++) {
                el[n0 * H + hbase + h] = el0[h];
                er[n0 * H + hbase + h] = er0[h];
                el[(n0 + 8) * H + hbase + h] = el8[h];
                er[(n0 + 8) * H + hbase + h] = er8[h];
            }
        }

        // ---- output: stage to smem, coalesced copy out ----
        __syncthreads();
        {
            int srow0 = t * 16 + g4;
#pragma unroll
            for (int nt = 0; nt < NTH; nt++) {
                int col = (ntbase + nt) * 8 + t4 * 2;
                *(__half2*)(XB + srow0 * SST + col) =
                    __floats2half2_rn(c[nt][0], c[nt][1]);
                *(__half2*)(XB + (srow0 + 8) * SST + col) =
                    __floats2half2_rn(c[nt][2], c[nt][3]);
            }
        }
        __syncthreads();
        {
            const int CH = HP / 8;
            __half* hg = hbuf + (size_t)tile * ROWS * HP;
            for (int u = tid; u < ROWS * CH; u += 256) {
                int row = u / CH, cc = u - row * CH;
                *(uint4*)(hg + row * HP + cc * 8) =
                    *(const uint4*)(XB + row * SST + cc * 8);
            }
        }
    }
}

// ---------------------------------------------------------------------------
// Single-pass warp-per-dst softmax + aggregation (fp16 hbuf rows HP=H*32).
template <int H, int OS, bool FC, typename OT>
__global__ void __launch_bounds__(256)
agg_kernel(const __half* __restrict__ hbuf,
           const float* __restrict__ el, const float* __restrict__ er,
           const int* __restrict__ loc, const int* __restrict__ bsum,
           const int* __restrict__ ssrc,
           const float* __restrict__ bias,
           OT* __restrict__ out,
           const float* __restrict__ fcw, const float* __restrict__ fcb,
           int n, int e) {
    const int HP = H * 32;
    const int L  = 4 * H;
    const int G  = 32 / L;
    const int LH = 4;
    const int QN = 8;

    int lane = threadIdx.x & 31;
    int w = (blockIdx.x * blockDim.x + threadIdx.x) >> 5;
    if (w >= n) return;

    int start = loc[w] + bsum[w >> 10];
    int end = (w + 1 < n) ? loc[w + 1] + bsum[(w + 1) >> 10] : e;

    const int g = lane / L;
    const int l = lane % L;
    const int head = l / LH;
    const int dbase = (l % LH) * QN;
    const bool sumlane = (l % LH) == 0;

    float er_l = er[w * H + head];
    float sum_l = 0.f;
    float acc[QN];
#pragma unroll
    for (int q = 0; q < QN; q++) acc[q] = 0.f;

    for (int j = start; j < end; j += G) {
        int jj = j + g;
        if (jj < end) {
            int s = __ldg(&ssrc[jj]);
            float qv = __ldg(&el[s * H + head]) + er_l;
            qv = (qv > 0.f) ? qv : 0.2f * qv;
            float ex = __expf(qv);
            if (sumlane) sum_l += ex;
            const __half* row = hbuf + (size_t)s * HP + l * QN;
            struct alignas(16) H8 { __half2 a, b, c, d; };
            H8 v = *(const H8*)row;
            float2 f0 = __half22float2(v.a);
            float2 f1 = __half22float2(v.b);
            float2 f2 = __half22float2(v.c);
            float2 f3 = __half22float2(v.d);
            acc[0] += ex * f0.x; acc[1] += ex * f0.y;
            acc[2] += ex * f1.x; acc[3] += ex * f1.y;
            acc[4] += ex * f2.x; acc[5] += ex * f2.y;
            acc[6] += ex * f3.x; acc[7] += ex * f3.y;
        }
    }

    sum_l += __shfl_xor_sync(0xffffffffu, sum_l, 1);
    sum_l += __shfl_xor_sync(0xffffffffu, sum_l, 2);
#pragma unroll
    for (int o = L; o < 32; o <<= 1) {
        sum_l += __shfl_xor_sync(0xffffffffu, sum_l, o);
#pragma unroll
        for (int q = 0; q < QN; q++)
            acc[q] += __shfl_xor_sync(0xffffffffu, acc[q], o);
    }

    float inv = 1.f / fmaxf(sum_l, 1e-9f);

    if constexpr (FC) {
        float z = 0.f;
        if (g == 0) {
#pragma unroll
            for (int q = 0; q < QN; q++) {
                int d = dbase + q;
                if (d < 25) z += (acc[q] * inv + bias[d]) * fcw[d];
            }
        }
#pragma unroll
        for (int o = 16; o > 0; o >>= 1) z += __shfl_xor_sync(0xffffffffu, z, o);
        if (lane == 0) out[w] = (OT)(1.f / (1.f + __expf(-(z + fcb[0]))));
    } else {
        if (g == 0) {
#pragma unroll
            for (int q = 0; q < QN; q++) {
                int d = dbase + q;
                if (d < 25) {
                    int f = head * 25 + d;
                    out[(size_t)w * OS + f] = (OT)(acc[q] * inv + bias[f]);
                }
            }
        }
    }
}

// ---------------------------------------------------------------------------
extern "C" void kernel_launch(void* const* d_in, const int* in_sizes, int n_in,
                              void* d_out, int out_size) {
    const float* feat = (const float*)d_in[0];
    const int*   src  = (const int*)d_in[1];
    const int*   dst  = (const int*)d_in[2];
    const float* W1   = (const float*)d_in[3];
    const float* al1  = (const float*)d_in[4];
    const float* ar1  = (const float*)d_in[5];
    const float* b1   = (const float*)d_in[6];
    const float* W2   = (const float*)d_in[7];
    const float* al2  = (const float*)d_in[8];
    const float* ar2  = (const float*)d_in[9];
    const float* b2   = (const float*)d_in[10];
    const float* W3   = (const float*)d_in[11];
    const float* al3  = (const float*)d_in[12];
    const float* ar3  = (const float*)d_in[13];
    const float* b3   = (const float*)d_in[14];
    const float* fcw  = (const float*)d_in[15];
    const float* fcb  = (const float*)d_in[16];
    float* out = (float*)d_out;

    int N = in_sizes[0] / 93;
    int E = in_sizes[1];
    int NB = (N + 1023) / 1024;
    int NP = ((N + 127) / 128) * 128;

    __half *xh1, *xh2, *xh3, *hh;
    float *el, *er;
    void* hraw;
    int *cnt, *rank, *loc, *bsum, *ssrc, *done;
    cudaGetSymbolAddress((void**)&xh1, g_xh1);
    cudaGetSymbolAddress(&hraw, g_h);
    cudaGetSymbolAddress((void**)&xh2, g_xh2);
    cudaGetSymbolAddress((void**)&xh3, g_xh3);
    cudaGetSymbolAddress((void**)&el, g_el);
    cudaGetSymbolAddress((void**)&er, g_er);
    cudaGetSymbolAddress((void**)&cnt, g_cnt);
    cudaGetSymbolAddress((void**)&rank, g_rank);
    cudaGetSymbolAddress((void**)&loc, g_loc);
    cudaGetSymbolAddress((void**)&bsum, g_bsum);
    cudaGetSymbolAddress((void**)&ssrc, g_ssrc);
    cudaGetSymbolAddress((void**)&done, g_done);
    hh = (__half*)hraw;

    int agrid = (N + 7) / 8;
    int hb = ((E + 3) / 4 + 255) / 256;
    int pb = (NP * 96 + 255) / 256;
    const int GG = 296;                    // 2 blocks/SM multi-tile gemm grid

    // launches: 0 hist(+convert+wt), 1 scan1, 2 scatter, 3 gemm1 (profiled),
    //           4 agg1, 5 gemm2, 6 agg2, 7 gemm3, 8 agg3
    hist_kernel<<<hb + pb + 8, 256>>>(dst, cnt, rank, E, hb, pb, feat, xh1, N, NP,
                                      W1, al1, ar1, W2, al2, ar2, W3, al3, ar3);
    scan1_kernel<<<NB, 1024>>>(cnt, loc, bsum, done, N, NB);
    scatter_kernel<<<hb, 256>>>(src, dst, loc, bsum, rank, ssrc, E);

    // layer1: H=4, 64-row tiles (WSPLIT=2)
    gemm_mma_kernel<96, 4, 2, WOFF1, AOFF1><<<GG, 256>>>(xh1, hh, el, er, NP / 64);
    agg_kernel<4, 112, false, __half><<<agrid, 256>>>(
        hh, el, er, loc, bsum, ssrc, b1, xh2, fcw, fcb, N, E);

    // layer2: H=2, 128-row tiles
    gemm_mma_kernel<112, 2, 1, WOFF2, AOFF2><<<GG, 256>>>(xh2, hh, el, er, NP / 128);
    agg_kernel<2, 64, false, __half><<<agrid, 256>>>(
        hh, el, er, loc, bsum, ssrc, b2, xh3, fcw, fcb, N, E);

    // layer3: H=1, 128-row tiles
    gemm_mma_kernel<64, 1, 1, WOFF3, AOFF3><<<GG, 256>>>(xh3, hh, el, er, NP / 128);
    agg_kernel<1, 1, true, float><<<agrid, 256>>>(
        hh, el, er, loc, bsum, ssrc, b3, out, fcw, fcb, N, E);
}

// round 16
// speedup vs baseline: 1.1331x; 1.1331x over previous
#include <cuda_runtime.h>
#include <cuda_fp16.h>
#include <cstdint>

// ---------------------------------------------------------------------------
// GAT 3-layer forward, fp16 feature path (fp32 attention math).
// hist: degree histogram + rank, plus one-time WT/al/ar staging blocks.
// GEMM: mma.sync m16n8k16, multi-tile blocks at 4 blocks/SM (GG=592);
//       layer1 fuses fp32->fp16 convert AND carries scatter blocks.
// CSR: warp-shfl scan (self-zeroing); scatter folded into gemm1.
// agg: single-pass warp-per-dst softmax+aggregate (profiled at slot 3).
// ---------------------------------------------------------------------------

#define NMAX 50000
#define NPMAX 50048          // multiple of 128
#define EMAX 800000
#define NBMAX 64

// WT layout (halfs): layer1 [0,13312) SP=104, layer2 [13312,20992) SP=120,
// layer3 [20992,23296) SP=72. al/ar tables: 128+64+32 = 224 floats.
#define WOFF1 0
#define WOFF2 13312
#define WOFF3 20992
#define WTOT  23296
#define AOFF1 0
#define AOFF2 128
#define AOFF3 192
#define ATOT  224

__device__ __align__(16) unsigned char g_h[NPMAX * 256];  // hbuf half rows HP=H*32
__device__ __align__(16) __half g_xh2[NPMAX * 112];       // agg1 out (L2 input)
__device__ __align__(16) __half g_xh3[NPMAX * 64];        // agg2 out (L3 input)
__device__ __align__(16) float g_el[NPMAX * 4];
__device__ __align__(16) float g_er[NPMAX * 4];
__device__ __align__(16) __half g_wt[WTOT];               // zero-init; pads stay 0
__device__ __align__(16) float g_alx[ATOT];
__device__ __align__(16) float g_arx[ATOT];
__device__ int   g_cnt[NMAX];    // ZERO at entry (load-init; re-zeroed by scan1)
__device__ int   g_rank[EMAX];
__device__ int   g_loc[NMAX];
__device__ int   g_bsum[NBMAX];
__device__ int   g_ssrc[EMAX];
__device__ int   g_done;         // ZERO at entry (reset by last scan1 block)

// ---------------------------------------------------------------------------
__device__ __forceinline__ void mma16816(float c[4], uint32_t a0, uint32_t a1,
                                         uint32_t a2, uint32_t a3,
                                         uint32_t b0, uint32_t b1) {
    asm volatile(
        "mma.sync.aligned.m16n8k16.row.col.f32.f16.f16.f32 "
        "{%0,%1,%2,%3}, {%4,%5,%6,%7}, {%8,%9}, {%0,%1,%2,%3};"
        : "+f"(c[0]), "+f"(c[1]), "+f"(c[2]), "+f"(c[3])
        : "r"(a0), "r"(a1), "r"(a2), "r"(a3), "r"(b0), "r"(b1));
}

__device__ __forceinline__ void ldsm_x4(uint32_t& r0, uint32_t& r1,
                                        uint32_t& r2, uint32_t& r3, uint32_t addr) {
    asm volatile("ldmatrix.sync.aligned.m8n8.x4.shared.b16 {%0,%1,%2,%3}, [%4];"
                 : "=r"(r0), "=r"(r1), "=r"(r2), "=r"(r3) : "r"(addr));
}

// ---------------------------------------------------------------------------
// hist: vectorized degree histogram with rank recording (blocks < hb), plus
// one-time WT/al/ar staging (8 trailing blocks). cnt zero at entry.
__global__ void hist_kernel(const int* __restrict__ dst, int* cnt, int* rank, int e,
                            int hb,
                            const float* __restrict__ W1, const float* __restrict__ al1,
                            const float* __restrict__ ar1,
                            const float* __restrict__ W2, const float* __restrict__ al2,
                            const float* __restrict__ ar2,
                            const float* __restrict__ W3, const float* __restrict__ al3,
                            const float* __restrict__ ar3) {
    int tid = threadIdx.x;
    if ((int)blockIdx.x < hb) {
        int i = (blockIdx.x * 256 + tid) * 4;
        if (i + 3 < e) {
            int4 d4 = *(const int4*)(dst + i);
            int4 r4;
            r4.x = atomicAdd(&cnt[d4.x], 1);
            r4.y = atomicAdd(&cnt[d4.y], 1);
            r4.z = atomicAdd(&cnt[d4.z], 1);
            r4.w = atomicAdd(&cnt[d4.w], 1);
            *(int4*)(rank + i) = r4;
        } else {
            for (int j = i; j < e; j++) rank[j] = atomicAdd(&cnt[dst[j]], 1);
        }
        return;
    }
    int b = blockIdx.x - hb;                 // 0..7 staging blocks
    for (int idx = b * 256 + tid; idx < WTOT; idx += 8 * 256) {
        float v = 0.f;
        int loc, sp, kr, col, k, d, h;
        if (idx < WOFF2) {
            loc = idx - WOFF1; sp = 104; kr = 93;
            col = loc / sp; k = loc - col * sp; d = col & 31; h = col >> 5;
            if (k < kr && d < 25) v = W1[k * 100 + h * 25 + d];
        } else if (idx < WOFF3) {
            loc = idx - WOFF2; sp = 120; kr = 100;
            col = loc / sp; k = loc - col * sp; d = col & 31; h = col >> 5;
            if (k < kr && d < 25) v = W2[k * 50 + h * 25 + d];
        } else {
            loc = idx - WOFF3; sp = 72; kr = 50;
            col = loc / sp; k = loc - col * sp; d = col & 31;
            if (k < kr && d < 25) v = W3[k * 25 + d];
        }
        g_wt[idx] = __float2half_rn(v);
    }
    for (int idx = b * 256 + tid; idx < ATOT; idx += 8 * 256) {
        int d = idx & 31;
        float va = 0.f, vr = 0.f;
        if (idx < AOFF2) {
            int h = idx >> 5;
            if (d < 25) { va = al1[h * 25 + d]; vr = ar1[h * 25 + d]; }
        } else if (idx < AOFF3) {
            int h = (idx - AOFF2) >> 5;
            if (d < 25) { va = al2[h * 25 + d]; vr = ar2[h * 25 + d]; }
        } else {
            if (d < 25) { va = al3[d]; vr = ar3[d]; }
        }
        g_alx[idx] = va;
        g_arx[idx] = vr;
    }
}

// per-chunk exclusive scan (warp-shfl) + fused cross-chunk scan; re-zeros cnt/done.
__global__ void scan1_kernel(int* cnt, int* loc, int* bsum,
                             int* done, int n, int nb) {
    __shared__ int wsum[32];
    __shared__ int last;
    int tid = threadIdx.x;
    int lane = tid & 31, wid = tid >> 5;
    int i = blockIdx.x * 1024 + tid;
    int v = (i < n) ? cnt[i] : 0;
    if (i < n) cnt[i] = 0;                 // restore zero invariant

    int x = v;
#pragma unroll
    for (int o = 1; o < 32; o <<= 1) {
        int t = __shfl_up_sync(0xffffffffu, x, o);
        if (lane >= o) x += t;
    }
    if (lane == 31) wsum[wid] = x;
    __syncthreads();
    if (wid == 0) {
        int y = wsum[lane];
        int z = y;
#pragma unroll
        for (int o = 1; o < 32; o <<= 1) {
            int t = __shfl_up_sync(0xffffffffu, z, o);
            if (lane >= o) z += t;
        }
        wsum[lane] = z - y;                // exclusive warp base
    }
    __syncthreads();
    int incl = x + wsum[wid];
    if (i < n) loc[i] = incl - v;
    if (tid == 1023) bsum[blockIdx.x] = incl;
    __threadfence();
    __syncthreads();
    if (tid == 0) last = (atomicAdd(done, 1) == gridDim.x - 1);
    __syncthreads();
    if (last) {
        if (tid < 32) {
            int a = (tid < nb) ? bsum[tid] : 0;
            int b = (tid + 32 < nb) ? bsum[tid + 32] : 0;
            int ai = a, bi = b;
#pragma unroll
            for (int o = 1; o < 32; o <<= 1) {
                int t = __shfl_up_sync(0xffffffffu, ai, o);
                if (tid >= o) ai += t;
            }
            int tot = __shfl_sync(0xffffffffu, ai, 31);
#pragma unroll
            for (int o = 1; o < 32; o <<= 1) {
                int t = __shfl_up_sync(0xffffffffu, bi, o);
                if (tid >= o) bi += t;
            }
            if (tid < nb) bsum[tid] = ai - a;
            if (tid + 32 < nb) bsum[tid + 32] = bi - b + tot;
        }
        if (tid == 0) *done = 0;           // restore zero invariant
    }
}

// ---------------------------------------------------------------------------
// fp16 tensor-core GEMM, multi-tile blocks (WT staged once per block).
// F32IN: x fp32 [nreal,93], converted during staging. SCAT: blocks >= gg run
// the vectorized atomic-free edge scatter instead (independent work).
template <int KP, int H, int WSPLIT, int WOFF, int AOFF, bool F32IN, bool SCAT>
__global__ void __launch_bounds__(256)
gemm_mma_kernel(const void* __restrict__ xin,
                __half* __restrict__ hbuf,
                float* __restrict__ el, float* __restrict__ er,
                int ntiles, int nreal, int gg,
                const int* __restrict__ src, const int* __restrict__ dst,
                const int* __restrict__ loc, const int* __restrict__ bsum,
                const int* __restrict__ rank, int* __restrict__ ssrc, int e) {
    if constexpr (SCAT) {
        if ((int)blockIdx.x >= gg) {
            int i = (((int)blockIdx.x - gg) * 256 + (int)threadIdx.x) * 4;
            if (i + 3 < e) {
                int4 d4 = *(const int4*)(dst + i);
                int4 s4 = *(const int4*)(src + i);
                int4 r4 = *(const int4*)(rank + i);
                ssrc[loc[d4.x] + bsum[d4.x >> 10] + r4.x] = s4.x;
                ssrc[loc[d4.y] + bsum[d4.y >> 10] + r4.y] = s4.y;
                ssrc[loc[d4.z] + bsum[d4.z >> 10] + r4.z] = s4.z;
                ssrc[loc[d4.w] + bsum[d4.w >> 10] + r4.w] = s4.w;
            } else {
                for (int j = i; j < e; j++) {
                    int d = dst[j];
                    ssrc[loc[d] + bsum[d >> 10] + rank[j]] = src[j];
                }
            }
            return;
        }
    }

    const int MT = H * 4;
    const int NTH = MT / WSPLIT;
    const int TILES = 8 / WSPLIT;
    const int ROWS = TILES * 16;
    const int SP  = KP + 8;
    const int HP  = H * 32;
    const int SST = HP + 8;
    const int XW  = (SP > SST) ? SP : SST;
    __shared__ __align__(16) __half WT[HP * SP];
    __shared__ __align__(16) __half XB[ROWS * XW];

    int tid = threadIdx.x;
    const __half* wtg = g_wt + WOFF;
    for (int idx = tid * 8; idx < HP * SP; idx += 256 * 8)
        *(uint4*)(WT + idx) = *(const uint4*)(wtg + idx);

    int wid = tid >> 5, lane = tid & 31;
    int g4 = lane >> 2, t4 = lane & 3;
    int t = wid / WSPLIT;
    int ntbase = (wid % WSPLIT) * NTH;     // multiple of 4
    const int HL = NTH / 4;
    const int hbase = ntbase / 4;

    int lm_row = lane & 7, sel = lane >> 3;
    int lm_nt = sel >> 1, lm_k = (sel & 1) * 8;
    uint32_t wt_u32 = (uint32_t)__cvta_generic_to_shared(WT)
        + (uint32_t)((((ntbase + lm_nt) * 8 + lm_row) * SP + lm_k) * 2);
    uint32_t xa_u32 = (uint32_t)__cvta_generic_to_shared(XB)
        + (uint32_t)(((t * 16 + (lane & 15)) * SP + (lane >> 4) * 8) * 2);

    const float* alxg = g_alx + AOFF;
    const float* arxg = g_arx + AOFF;

    for (int tile = blockIdx.x; tile < ntiles; tile += gg) {
        __syncthreads();
        // ---- stage x-tile ----
        if constexpr (F32IN) {
            const int RW = 93;
            for (int u = tid; u < ROWS * SP / 8; u += 256)
                *(uint4*)(XB + u * 8) = make_uint4(0, 0, 0, 0);
            __syncthreads();
            const float* feat = (const float*)xin;
            int base = tile * ROWS * RW;
            int lim = nreal * RW;
            for (int u = tid; u < ROWS * RW / 4; u += 256) {
                int f = u * 4;
                float v[4];
                if (base + f + 3 < lim) {
                    float4 q = *(const float4*)(feat + base + f);
                    v[0] = q.x; v[1] = q.y; v[2] = q.z; v[3] = q.w;
                } else {
#pragma unroll
                    for (int j = 0; j < 4; j++)
                        v[j] = (base + f + j < lim) ? feat[base + f + j] : 0.f;
                }
#pragma unroll
                for (int j = 0; j < 4; j++) {
                    int ff = f + j;
                    int r = ff / RW, k = ff - r * RW;
                    XB[r * SP + k] = __float2half_rn(v[j]);
                }
            }
        } else {
            const __half* xg = (const __half*)xin + (size_t)tile * ROWS * KP;
            const int CRX = KP / 8;
            for (int u = tid; u < ROWS * CRX; u += 256) {
                int row = u / CRX, c = u - row * CRX;
                *(uint4*)(XB + row * SP + c * 8) =
                    *(const uint4*)(xg + row * KP + c * 8);
            }
        }
        __syncthreads();

        // ---- mainloop ----
        float c[NTH][4];
#pragma unroll
        for (int nt = 0; nt < NTH; nt++)
#pragma unroll
            for (int q = 0; q < 4; q++) c[nt][q] = 0.f;

#pragma unroll
        for (int ks = 0; ks < KP / 16; ks++) {
            uint32_t a0, a1, a2, a3;
            ldsm_x4(a0, a1, a2, a3, xa_u32 + (uint32_t)(ks * 32));
#pragma unroll
            for (int ntp = 0; ntp < NTH / 2; ntp++) {
                uint32_t b00, b01, b10, b11;
                uint32_t addr = wt_u32 + (uint32_t)((ntp * 16 * SP + ks * 16) * 2);
                ldsm_x4(b00, b01, b10, b11, addr);
                mma16816(c[2 * ntp], a0, a1, a2, a3, b00, b01);
                mma16816(c[2 * ntp + 1], a0, a1, a2, a3, b10, b11);
            }
        }

        // ---- el/er epilogue ----
        int m0 = tile * ROWS + t * 16;
        float el0[HL], er0[HL], el8[HL], er8[HL];
#pragma unroll
        for (int h = 0; h < HL; h++) { el0[h] = er0[h] = el8[h] = er8[h] = 0.f; }
#pragma unroll
        for (int nt = 0; nt < NTH; nt++) {
            int col = (ntbase + nt) * 8 + t4 * 2;
            int h = nt >> 2;
            float2 av = *(const float2*)&alxg[col];
            float2 rv = *(const float2*)&arxg[col];
            el0[h] += c[nt][0] * av.x + c[nt][1] * av.y;
            er0[h] += c[nt][0] * rv.x + c[nt][1] * rv.y;
            el8[h] += c[nt][2] * av.x + c[nt][3] * av.y;
            er8[h] += c[nt][2] * rv.x + c[nt][3] * rv.y;
        }
#pragma unroll
        for (int h = 0; h < HL; h++) {
#pragma unroll
            for (int o = 1; o <= 2; o <<= 1) {
                el0[h] += __shfl_xor_sync(0xffffffffu, el0[h], o);
                er0[h] += __shfl_xor_sync(0xffffffffu, er0[h], o);
                el8[h] += __shfl_xor_sync(0xffffffffu, el8[h], o);
                er8[h] += __shfl_xor_sync(0xffffffffu, er8[h], o);
            }
        }
        if (t4 == 0) {
            int n0 = m0 + g4;
#pragma unroll
            for (int h = 0; h < HL; h++) {
                el[n0 * H + hbase + h] = el0[h];
                er[n0 * H + hbase + h] = er0[h];
                el[(n0 + 8) * H + hbase + h] = el8[h];
                er[(n0 + 8) * H + hbase + h] = er8[h];
            }
        }

        // ---- output: stage to smem, coalesced copy out ----
        __syncthreads();
        {
            int srow0 = t * 16 + g4;
#pragma unroll
            for (int nt = 0; nt < NTH; nt++) {
                int col = (ntbase + nt) * 8 + t4 * 2;
                *(__half2*)(XB + srow0 * SST + col) =
                    __floats2half2_rn(c[nt][0], c[nt][1]);
                *(__half2*)(XB + (srow0 + 8) * SST + col) =
                    __floats2half2_rn(c[nt][2], c[nt][3]);
            }
        }
        __syncthreads();
        {
            const int CH = HP / 8;
            __half* hg = hbuf + (size_t)tile * ROWS * HP;
            for (int u = tid; u < ROWS * CH; u += 256) {
                int row = u / CH, cc = u - row * CH;
                *(uint4*)(hg + row * HP + cc * 8) =
                    *(const uint4*)(XB + row * SST + cc * 8);
            }
        }
    }
}

// ---------------------------------------------------------------------------
// Single-pass warp-per-dst softmax + aggregation (fp16 hbuf rows HP=H*32).
template <int H, int OS, bool FC, typename OT>
__global__ void __launch_bounds__(256)
agg_kernel(const __half* __restrict__ hbuf,
           const float* __restrict__ el, const float* __restrict__ er,
           const int* __restrict__ loc, const int* __restrict__ bsum,
           const int* __restrict__ ssrc,
           const float* __restrict__ bias,
           OT* __restrict__ out,
           const float* __restrict__ fcw, const float* __restrict__ fcb,
           int n, int e) {
    const int HP = H * 32;
    const int L  = 4 * H;
    const int G  = 32 / L;
    const int LH = 4;
    const int QN = 8;

    int lane = threadIdx.x & 31;
    int w = (blockIdx.x * blockDim.x + threadIdx.x) >> 5;
    if (w >= n) return;

    int start = loc[w] + bsum[w >> 10];
    int end = (w + 1 < n) ? loc[w + 1] + bsum[(w + 1) >> 10] : e;

    const int g = lane / L;
    const int l = lane % L;
    const int head = l / LH;
    const int dbase = (l % LH) * QN;
    const bool sumlane = (l % LH) == 0;

    float er_l = er[w * H + head];
    float sum_l = 0.f;
    float acc[QN];
#pragma unroll
    for (int q = 0; q < QN; q++) acc[q] = 0.f;

    for (int j = start; j < end; j += G) {
        int jj = j + g;
        if (jj < end) {
            int s = __ldg(&ssrc[jj]);
            float qv = __ldg(&el[s * H + head]) + er_l;
            qv = (qv > 0.f) ? qv : 0.2f * qv;
            float ex = __expf(qv);
            if (sumlane) sum_l += ex;
            const __half* row = hbuf + (size_t)s * HP + l * QN;
            struct alignas(16) H8 { __half2 a, b, c, d; };
            H8 v = *(const H8*)row;
            float2 f0 = __half22float2(v.a);
            float2 f1 = __half22float2(v.b);
            float2 f2 = __half22float2(v.c);
            float2 f3 = __half22float2(v.d);
            acc[0] += ex * f0.x; acc[1] += ex * f0.y;
            acc[2] += ex * f1.x; acc[3] += ex * f1.y;
            acc[4] += ex * f2.x; acc[5] += ex * f2.y;
            acc[6] += ex * f3.x; acc[7] += ex * f3.y;
        }
    }

    sum_l += __shfl_xor_sync(0xffffffffu, sum_l, 1);
    sum_l += __shfl_xor_sync(0xffffffffu, sum_l, 2);
#pragma unroll
    for (int o = L; o < 32; o <<= 1) {
        sum_l += __shfl_xor_sync(0xffffffffu, sum_l, o);
#pragma unroll
        for (int q = 0; q < QN; q++)
            acc[q] += __shfl_xor_sync(0xffffffffu, acc[q], o);
    }

    float inv = 1.f / fmaxf(sum_l, 1e-9f);

    if constexpr (FC) {
        float z = 0.f;
        if (g == 0) {
#pragma unroll
            for (int q = 0; q < QN; q++) {
                int d = dbase + q;
                if (d < 25) z += (acc[q] * inv + bias[d]) * fcw[d];
            }
        }
#pragma unroll
        for (int o = 16; o > 0; o >>= 1) z += __shfl_xor_sync(0xffffffffu, z, o);
        if (lane == 0) out[w] = (OT)(1.f / (1.f + __expf(-(z + fcb[0]))));
    } else {
        if (g == 0) {
#pragma unroll
            for (int q = 0; q < QN; q++) {
                int d = dbase + q;
                if (d < 25) {
                    int f = head * 25 + d;
                    out[(size_t)w * OS + f] = (OT)(acc[q] * inv + bias[f]);
                }
            }
        }
    }
}

// ---------------------------------------------------------------------------
extern "C" void kernel_launch(void* const* d_in, const int* in_sizes, int n_in,
                              void* d_out, int out_size) {
    const float* feat = (const float*)d_in[0];
    const int*   src  = (const int*)d_in[1];
    const int*   dst  = (const int*)d_in[2];
    const float* W1   = (const float*)d_in[3];
    const float* al1  = (const float*)d_in[4];
    const float* ar1  = (const float*)d_in[5];
    const float* b1   = (const float*)d_in[6];
    const float* W2   = (const float*)d_in[7];
    const float* al2  = (const float*)d_in[8];
    const float* ar2  = (const float*)d_in[9];
    const float* b2   = (const float*)d_in[10];
    const float* W3   = (const float*)d_in[11];
    const float* al3  = (const float*)d_in[12];
    const float* ar3  = (const float*)d_in[13];
    const float* b3   = (const float*)d_in[14];
    const float* fcw  = (const float*)d_in[15];
    const float* fcb  = (const float*)d_in[16];
    float* out = (float*)d_out;

    int N = in_sizes[0] / 93;
    int E = in_sizes[1];
    int NB = (N + 1023) / 1024;
    int NP = ((N + 127) / 128) * 128;

    __half *xh2, *xh3, *hh;
    float *el, *er;
    void* hraw;
    int *cnt, *rank, *loc, *bsum, *ssrc, *done;
    cudaGetSymbolAddress(&hraw, g_h);
    cudaGetSymbolAddress((void**)&xh2, g_xh2);
    cudaGetSymbolAddress((void**)&xh3, g_xh3);
    cudaGetSymbolAddress((void**)&el, g_el);
    cudaGetSymbolAddress((void**)&er, g_er);
    cudaGetSymbolAddress((void**)&cnt, g_cnt);
    cudaGetSymbolAddress((void**)&rank, g_rank);
    cudaGetSymbolAddress((void**)&loc, g_loc);
    cudaGetSymbolAddress((void**)&bsum, g_bsum);
    cudaGetSymbolAddress((void**)&ssrc, g_ssrc);
    cudaGetSymbolAddress((void**)&done, g_done);
    hh = (__half*)hraw;

    int agrid = (N + 7) / 8;
    int hb = ((E + 3) / 4 + 255) / 256;
    const int GG = 592;                    // 4 blocks/SM gemm grid

    // launches: 0 hist(+wt), 1 scan1, 2 gemm1(+scatter), 3 agg1 (profiled),
    //           4 gemm2, 5 agg2, 6 gemm3, 7 agg3
    hist_kernel<<<hb + 8, 256>>>(dst, cnt, rank, E, hb,
                                 W1, al1, ar1, W2, al2, ar2, W3, al3, ar3);
    scan1_kernel<<<NB, 1024>>>(cnt, loc, bsum, done, N, NB);

    // layer1: H=4, 64-row tiles, fp32 input (fused convert) + scatter blocks
    gemm_mma_kernel<96, 4, 2, WOFF1, AOFF1, true, true><<<GG + hb, 256>>>(
        feat, hh, el, er, NP / 64, N, GG,
        src, dst, loc, bsum, rank, ssrc, E);
    agg_kernel<4, 112, false, __half><<<agrid, 256>>>(
        hh, el, er, loc, bsum, ssrc, b1, xh2, fcw, fcb, N, E);

    // layer2: H=2, 64-row tiles (WSPLIT=2), fp16 input stride 112
    gemm_mma_kernel<112, 2, 2, WOFF2, AOFF2, false, false><<<GG, 256>>>(
        xh2, hh, el, er, NP / 64, N, GG,
        nullptr, nullptr, nullptr, nullptr, nullptr, nullptr, 0);
    agg_kernel<2, 64, false, __half><<<agrid, 256>>>(
        hh, el, er, loc, bsum, ssrc, b2, xh3, fcw, fcb, N, E);

    // layer3: H=1, 128-row tiles, fp16 input stride 64
    gemm_mma_kernel<64, 1, 1, WOFF3, AOFF3, false, false><<<NP / 128, 256>>>(
        xh3, hh, el, er, NP / 128, N, NP / 128,
        nullptr, nullptr, nullptr, nullptr, nullptr, nullptr, 0);
    agg_kernel<1, 1, true, float><<<agrid, 256>>>(
        hh, el, er, loc, bsum, ssrc, b3, out, fcw, fcb, N, E);
}

// round 17
// speedup vs baseline: 1.1455x; 1.0109x over previous
#include <cuda_runtime.h>
#include <cuda_fp16.h>
#include <cstdint>

// ---------------------------------------------------------------------------
// GAT 3-layer forward, fp16 feature path (fp32 attention math).
// el is transported bit-exactly inside the hbuf row padding (slots 26,27 of
// each head) -> agg's 16B row gather carries el for free; no el array at all.
// hist: degree histogram + rank + one-time WT/al/ar staging blocks.
// GEMM: mma.sync m16n8k16, multi-tile blocks at 4 blocks/SM; layer1 fuses
// fp32->fp16 convert and carries the scatter blocks.
// agg: single-pass warp-per-dst softmax+aggregate, convergent loop.
// ---------------------------------------------------------------------------

#define NMAX 50000
#define NPMAX 50048          // multiple of 128
#define EMAX 800000
#define NBMAX 64

#define WOFF1 0
#define WOFF2 13312
#define WOFF3 20992
#define WTOT  23296
#define AOFF1 0
#define AOFF2 128
#define AOFF3 192
#define ATOT  224

__device__ __align__(16) unsigned char g_h[NPMAX * 256];  // hbuf half rows HP=H*32
__device__ __align__(16) __half g_xh2[NPMAX * 112];       // agg1 out (L2 input)
__device__ __align__(16) __half g_xh3[NPMAX * 64];        // agg2 out (L3 input)
__device__ __align__(16) float g_er[NPMAX * 4];
__device__ __align__(16) __half g_wt[WTOT];               // zero-init; pads stay 0
__device__ __align__(16) float g_alx[ATOT];
__device__ __align__(16) float g_arx[ATOT];
__device__ int   g_cnt[NMAX];    // ZERO at entry (load-init; re-zeroed by scan1)
__device__ int   g_rank[EMAX];
__device__ int   g_loc[NMAX];
__device__ int   g_bsum[NBMAX];
__device__ int   g_ssrc[EMAX];
__device__ int   g_done;         // ZERO at entry (reset by last scan1 block)

// ---------------------------------------------------------------------------
__device__ __forceinline__ void mma16816(float c[4], uint32_t a0, uint32_t a1,
                                         uint32_t a2, uint32_t a3,
                                         uint32_t b0, uint32_t b1) {
    asm volatile(
        "mma.sync.aligned.m16n8k16.row.col.f32.f16.f16.f32 "
        "{%0,%1,%2,%3}, {%4,%5,%6,%7}, {%8,%9}, {%0,%1,%2,%3};"
        : "+f"(c[0]), "+f"(c[1]), "+f"(c[2]), "+f"(c[3])
        : "r"(a0), "r"(a1), "r"(a2), "r"(a3), "r"(b0), "r"(b1));
}

__device__ __forceinline__ void ldsm_x4(uint32_t& r0, uint32_t& r1,
                                        uint32_t& r2, uint32_t& r3, uint32_t addr) {
    asm volatile("ldmatrix.sync.aligned.m8n8.x4.shared.b16 {%0,%1,%2,%3}, [%4];"
                 : "=r"(r0), "=r"(r1), "=r"(r2), "=r"(r3) : "r"(addr));
}

__device__ __forceinline__ uint32_t h2_as_u32(__half2 v) {
    uint32_t r;
    memcpy(&r, &v, 4);
    return r;
}

// ---------------------------------------------------------------------------
// hist: vectorized degree histogram with rank (blocks < hb) + one-time
// WT/al/ar staging (8 trailing blocks). cnt zero at entry.
__global__ void hist_kernel(const int* __restrict__ dst, int* cnt, int* rank, int e,
                            int hb,
                            const float* __restrict__ W1, const float* __restrict__ al1,
                            const float* __restrict__ ar1,
                            const float* __restrict__ W2, const float* __restrict__ al2,
                            const float* __restrict__ ar2,
                            const float* __restrict__ W3, const float* __restrict__ al3,
                            const float* __restrict__ ar3) {
    int tid = threadIdx.x;
    if ((int)blockIdx.x < hb) {
        int i = (blockIdx.x * 256 + tid) * 4;
        if (i + 3 < e) {
            int4 d4 = *(const int4*)(dst + i);
            int4 r4;
            r4.x = atomicAdd(&cnt[d4.x], 1);
            r4.y = atomicAdd(&cnt[d4.y], 1);
            r4.z = atomicAdd(&cnt[d4.z], 1);
            r4.w = atomicAdd(&cnt[d4.w], 1);
            *(int4*)(rank + i) = r4;
        } else {
            for (int j = i; j < e; j++) rank[j] = atomicAdd(&cnt[dst[j]], 1);
        }
        return;
    }
    int b = blockIdx.x - hb;
    for (int idx = b * 256 + tid; idx < WTOT; idx += 8 * 256) {
        float v = 0.f;
        int loc, sp, kr, col, k, d, h;
        if (idx < WOFF2) {
            loc = idx - WOFF1; sp = 104; kr = 93;
            col = loc / sp; k = loc - col * sp; d = col & 31; h = col >> 5;
            if (k < kr && d < 25) v = W1[k * 100 + h * 25 + d];
        } else if (idx < WOFF3) {
            loc = idx - WOFF2; sp = 120; kr = 100;
            col = loc / sp; k = loc - col * sp; d = col & 31; h = col >> 5;
            if (k < kr && d < 25) v = W2[k * 50 + h * 25 + d];
        } else {
            loc = idx - WOFF3; sp = 72; kr = 50;
            col = loc / sp; k = loc - col * sp; d = col & 31;
            if (k < kr && d < 25) v = W3[k * 25 + d];
        }
        g_wt[idx] = __float2half_rn(v);
    }
    for (int idx = b * 256 + tid; idx < ATOT; idx += 8 * 256) {
        int d = idx & 31;
        float va = 0.f, vr = 0.f;
        if (idx < AOFF2) {
            int h = idx >> 5;
            if (d < 25) { va = al1[h * 25 + d]; vr = ar1[h * 25 + d]; }
        } else if (idx < AOFF3) {
            int h = (idx - AOFF2) >> 5;
            if (d < 25) { va = al2[h * 25 + d]; vr = ar2[h * 25 + d]; }
        } else {
            if (d < 25) { va = al3[d]; vr = ar3[d]; }
        }
        g_alx[idx] = va;
        g_arx[idx] = vr;
    }
}

// per-chunk exclusive scan (warp-shfl) + fused cross-chunk scan; re-zeros cnt/done.
__global__ void scan1_kernel(int* cnt, int* loc, int* bsum,
                             int* done, int n, int nb) {
    __shared__ int wsum[32];
    __shared__ int last;
    int tid = threadIdx.x;
    int lane = tid & 31, wid = tid >> 5;
    int i = blockIdx.x * 1024 + tid;
    int v = (i < n) ? cnt[i] : 0;
    if (i < n) cnt[i] = 0;

    int x = v;
#pragma unroll
    for (int o = 1; o < 32; o <<= 1) {
        int t = __shfl_up_sync(0xffffffffu, x, o);
        if (lane >= o) x += t;
    }
    if (lane == 31) wsum[wid] = x;
    __syncthreads();
    if (wid == 0) {
        int y = wsum[lane];
        int z = y;
#pragma unroll
        for (int o = 1; o < 32; o <<= 1) {
            int t = __shfl_up_sync(0xffffffffu, z, o);
            if (lane >= o) z += t;
        }
        wsum[lane] = z - y;
    }
    __syncthreads();
    int incl = x + wsum[wid];
    if (i < n) loc[i] = incl - v;
    if (tid == 1023) bsum[blockIdx.x] = incl;
    __threadfence();
    __syncthreads();
    if (tid == 0) last = (atomicAdd(done, 1) == gridDim.x - 1);
    __syncthreads();
    if (last) {
        if (tid < 32) {
            int a = (tid < nb) ? bsum[tid] : 0;
            int b = (tid + 32 < nb) ? bsum[tid + 32] : 0;
            int ai = a, bi = b;
#pragma unroll
            for (int o = 1; o < 32; o <<= 1) {
                int t = __shfl_up_sync(0xffffffffu, ai, o);
                if (tid >= o) ai += t;
            }
            int tot = __shfl_sync(0xffffffffu, ai, 31);
#pragma unroll
            for (int o = 1; o < 32; o <<= 1) {
                int t = __shfl_up_sync(0xffffffffu, bi, o);
                if (tid >= o) bi += t;
            }
            if (tid < nb) bsum[tid] = ai - a;
            if (tid + 32 < nb) bsum[tid + 32] = bi - b + tot;
        }
        if (tid == 0) *done = 0;
    }
}

// ---------------------------------------------------------------------------
// fp16 tensor-core GEMM, multi-tile blocks. F32IN: convert fp32 feat during
// staging. SCAT: blocks >= gg run the atomic-free edge scatter.
// el embedded bit-exactly into hbuf pad slots (26,27) of each head.
template <int KP, int H, int WSPLIT, int WOFF, int AOFF, bool F32IN, bool SCAT>
__global__ void __launch_bounds__(256)
gemm_mma_kernel(const void* __restrict__ xin,
                __half* __restrict__ hbuf,
                float* __restrict__ er,
                int ntiles, int nreal, int gg,
                const int* __restrict__ src, const int* __restrict__ dst,
                const int* __restrict__ loc, const int* __restrict__ bsum,
                const int* __restrict__ rank, int* __restrict__ ssrc, int e) {
    if constexpr (SCAT) {
        if ((int)blockIdx.x >= gg) {
            int i = (((int)blockIdx.x - gg) * 256 + (int)threadIdx.x) * 4;
            if (i + 3 < e) {
                int4 d4 = *(const int4*)(dst + i);
                int4 s4 = *(const int4*)(src + i);
                int4 r4 = *(const int4*)(rank + i);
                ssrc[loc[d4.x] + bsum[d4.x >> 10] + r4.x] = s4.x;
                ssrc[loc[d4.y] + bsum[d4.y >> 10] + r4.y] = s4.y;
                ssrc[loc[d4.z] + bsum[d4.z >> 10] + r4.z] = s4.z;
                ssrc[loc[d4.w] + bsum[d4.w >> 10] + r4.w] = s4.w;
            } else {
                for (int j = i; j < e; j++) {
                    int d = dst[j];
                    ssrc[loc[d] + bsum[d >> 10] + rank[j]] = src[j];
                }
            }
            return;
        }
    }

    const int MT = H * 4;
    const int NTH = MT / WSPLIT;
    const int TILES = 8 / WSPLIT;
    const int ROWS = TILES * 16;
    const int SP  = KP + 8;
    const int HP  = H * 32;
    const int SST = HP + 8;
    const int XW  = (SP > SST) ? SP : SST;
    __shared__ __align__(16) __half WT[HP * SP];
    __shared__ __align__(16) __half XB[ROWS * XW];

    int tid = threadIdx.x;
    const __half* wtg = g_wt + WOFF;
    for (int idx = tid * 8; idx < HP * SP; idx += 256 * 8)
        *(uint4*)(WT + idx) = *(const uint4*)(wtg + idx);

    int wid = tid >> 5, lane = tid & 31;
    int g4 = lane >> 2, t4 = lane & 3;
    int t = wid / WSPLIT;
    int ntbase = (wid % WSPLIT) * NTH;     // multiple of 4
    const int HL = NTH / 4;
    const int hbase = ntbase / 4;

    int lm_row = lane & 7, sel = lane >> 3;
    int lm_nt = sel >> 1, lm_k = (sel & 1) * 8;
    uint32_t wt_u32 = (uint32_t)__cvta_generic_to_shared(WT)
        + (uint32_t)((((ntbase + lm_nt) * 8 + lm_row) * SP + lm_k) * 2);
    uint32_t xa_u32 = (uint32_t)__cvta_generic_to_shared(XB)
        + (uint32_t)(((t * 16 + (lane & 15)) * SP + (lane >> 4) * 8) * 2);

    const float* alxg = g_alx + AOFF;
    const float* arxg = g_arx + AOFF;

    for (int tile = blockIdx.x; tile < ntiles; tile += gg) {
        __syncthreads();
        // ---- stage x-tile ----
        if constexpr (F32IN) {
            const int RW = 93;
            for (int u = tid; u < ROWS * SP / 8; u += 256)
                *(uint4*)(XB + u * 8) = make_uint4(0, 0, 0, 0);
            __syncthreads();
            const float* feat = (const float*)xin;
            int base = tile * ROWS * RW;
            int lim = nreal * RW;
            for (int u = tid; u < ROWS * RW / 4; u += 256) {
                int f = u * 4;
                float v[4];
                if (base + f + 3 < lim) {
                    float4 q = *(const float4*)(feat + base + f);
                    v[0] = q.x; v[1] = q.y; v[2] = q.z; v[3] = q.w;
                } else {
#pragma unroll
                    for (int j = 0; j < 4; j++)
                        v[j] = (base + f + j < lim) ? feat[base + f + j] : 0.f;
                }
#pragma unroll
                for (int j = 0; j < 4; j++) {
                    int ff = f + j;
                    int r = ff / RW, k = ff - r * RW;
                    XB[r * SP + k] = __float2half_rn(v[j]);
                }
            }
        } else {
            const __half* xg = (const __half*)xin + (size_t)tile * ROWS * KP;
            const int CRX = KP / 8;
            for (int u = tid; u < ROWS * CRX; u += 256) {
                int row = u / CRX, c = u - row * CRX;
                *(uint4*)(XB + row * SP + c * 8) =
                    *(const uint4*)(xg + row * KP + c * 8);
            }
        }
        __syncthreads();

        // ---- mainloop ----
        float c[NTH][4];
#pragma unroll
        for (int nt = 0; nt < NTH; nt++)
#pragma unroll
            for (int q = 0; q < 4; q++) c[nt][q] = 0.f;

#pragma unroll
        for (int ks = 0; ks < KP / 16; ks++) {
            uint32_t a0, a1, a2, a3;
            ldsm_x4(a0, a1, a2, a3, xa_u32 + (uint32_t)(ks * 32));
#pragma unroll
            for (int ntp = 0; ntp < NTH / 2; ntp++) {
                uint32_t b00, b01, b10, b11;
                uint32_t addr = wt_u32 + (uint32_t)((ntp * 16 * SP + ks * 16) * 2);
                ldsm_x4(b00, b01, b10, b11, addr);
                mma16816(c[2 * ntp], a0, a1, a2, a3, b00, b01);
                mma16816(c[2 * ntp + 1], a0, a1, a2, a3, b10, b11);
            }
        }

        // ---- el/er epilogue (quad-uniform after butterfly) ----
        int m0 = tile * ROWS + t * 16;
        float el0[HL], er0[HL], el8[HL], er8[HL];
#pragma unroll
        for (int h = 0; h < HL; h++) { el0[h] = er0[h] = el8[h] = er8[h] = 0.f; }
#pragma unroll
        for (int nt = 0; nt < NTH; nt++) {
            int col = (ntbase + nt) * 8 + t4 * 2;
            int h = nt >> 2;
            float2 av = *(const float2*)&alxg[col];
            float2 rv = *(const float2*)&arxg[col];
            el0[h] += c[nt][0] * av.x + c[nt][1] * av.y;
            er0[h] += c[nt][0] * rv.x + c[nt][1] * rv.y;
            el8[h] += c[nt][2] * av.x + c[nt][3] * av.y;
            er8[h] += c[nt][2] * rv.x + c[nt][3] * rv.y;
        }
#pragma unroll
        for (int h = 0; h < HL; h++) {
#pragma unroll
            for (int o = 1; o <= 2; o <<= 1) {
                el0[h] += __shfl_xor_sync(0xffffffffu, el0[h], o);
                er0[h] += __shfl_xor_sync(0xffffffffu, er0[h], o);
                el8[h] += __shfl_xor_sync(0xffffffffu, el8[h], o);
                er8[h] += __shfl_xor_sync(0xffffffffu, er8[h], o);
            }
        }
        if (t4 == 0) {
            int n0 = m0 + g4;
#pragma unroll
            for (int h = 0; h < HL; h++) {
                er[n0 * H + hbase + h] = er0[h];
                er[(n0 + 8) * H + hbase + h] = er8[h];
            }
        }

        // ---- output: stage to smem (embed el bits), coalesced copy out ----
        __syncthreads();
        {
            int srow0 = t * 16 + g4;
#pragma unroll
            for (int nt = 0; nt < NTH; nt++) {
                int col = (ntbase + nt) * 8 + t4 * 2;
                uint32_t w0 = h2_as_u32(__floats2half2_rn(c[nt][0], c[nt][1]));
                uint32_t w8 = h2_as_u32(__floats2half2_rn(c[nt][2], c[nt][3]));
                if (((ntbase + nt) & 3) == 3 && t4 == 1) {
                    int h = nt >> 2;               // cols 26,27 of this head
                    w0 = __float_as_uint(el0[h]);
                    w8 = __float_as_uint(el8[h]);
                }
                *(uint32_t*)(XB + srow0 * SST + col) = w0;
                *(uint32_t*)(XB + (srow0 + 8) * SST + col) = w8;
            }
        }
        __syncthreads();
        {
            const int CH = HP / 8;
            __half* hg = hbuf + (size_t)tile * ROWS * HP;
            for (int u = tid; u < ROWS * CH; u += 256) {
                int row = u / CH, cc = u - row * CH;
                *(uint4*)(hg + row * HP + cc * 8) =
                    *(const uint4*)(XB + row * SST + cc * 8);
            }
        }
    }
}

// ---------------------------------------------------------------------------
// Single-pass warp-per-dst softmax + aggregation. el arrives embedded in the
// gathered row (pad slots 26,27 -> l%4==3 lane's v.b); shfl-broadcast per quad.
// Convergent loop (index clamp + ex=0 masking).
template <int H, int OS, bool FC, typename OT>
__global__ void __launch_bounds__(256)
agg_kernel(const __half* __restrict__ hbuf,
           const float* __restrict__ er,
           const int* __restrict__ loc, const int* __restrict__ bsum,
           const int* __restrict__ ssrc,
           const float* __restrict__ bias,
           OT* __restrict__ out,
           const float* __restrict__ fcw, const float* __restrict__ fcb,
           int n, int e) {
    const int HP = H * 32;
    const int L  = 4 * H;
    const int G  = 32 / L;
    const int QN = 8;

    int lane = threadIdx.x & 31;
    int w = (blockIdx.x * blockDim.x + threadIdx.x) >> 5;
    if (w >= n) return;

    int start = loc[w] + bsum[w >> 10];
    int end = (w + 1 < n) ? loc[w + 1] + bsum[(w + 1) >> 10] : e;

    const int g = lane / L;
    const int l = lane % L;
    const int head = l >> 2;
    const int dbase = (l & 3) * QN;
    const bool sumlane = (l & 3) == 0;

    float er_l = er[w * H + head];
    float sum_l = 0.f;
    float acc[QN];
#pragma unroll
    for (int q = 0; q < QN; q++) acc[q] = 0.f;

    for (int j = start; j < end; j += G) {
        int jj = j + g;
        bool ok = (jj < end);
        int jjc = ok ? jj : (end - 1);          // start<end inside loop
        int s = __ldg(&ssrc[jjc]);
        const __half* row = hbuf + (size_t)s * HP + l * QN;
        struct alignas(16) H8 { __half2 a, b, c, d; };
        H8 v = *(const H8*)row;
        // el bits live in v.b of the (l&3)==3 lane of each quad
        uint32_t eb;
        memcpy(&eb, &v.b, 4);
        uint32_t ebl = __shfl_sync(0xffffffffu, eb, lane | 3);
        float qv = __uint_as_float(ebl) + er_l;
        qv = (qv > 0.f) ? qv : 0.2f * qv;
        float ex = __expf(qv);
        if (!ok) ex = 0.f;
        if (sumlane) sum_l += ex;
        float2 f0 = __half22float2(v.a);
        float2 f1 = __half22float2(v.b);
        float2 f2 = __half22float2(v.c);
        float2 f3 = __half22float2(v.d);
        acc[0] += ex * f0.x; acc[1] += ex * f0.y;
        acc[2] += ex * f1.x; acc[3] += ex * f1.y;
        acc[4] += ex * f2.x; acc[5] += ex * f2.y;
        acc[6] += ex * f3.x; acc[7] += ex * f3.y;
    }

    sum_l += __shfl_xor_sync(0xffffffffu, sum_l, 1);
    sum_l += __shfl_xor_sync(0xffffffffu, sum_l, 2);
#pragma unroll
    for (int o = L; o < 32; o <<= 1) {
        sum_l += __shfl_xor_sync(0xffffffffu, sum_l, o);
#pragma unroll
        for (int q = 0; q < QN; q++)
            acc[q] += __shfl_xor_sync(0xffffffffu, acc[q], o);
    }

    float inv = 1.f / fmaxf(sum_l, 1e-9f);

    if constexpr (FC) {
        float z = 0.f;
        if (g == 0) {
#pragma unroll
            for (int q = 0; q < QN; q++) {
                int d = dbase + q;
                if (d < 25) z += (acc[q] * inv + bias[d]) * fcw[d];
            }
        }
#pragma unroll
        for (int o = 16; o > 0; o >>= 1) z += __shfl_xor_sync(0xffffffffu, z, o);
        if (lane == 0) out[w] = (OT)(1.f / (1.f + __expf(-(z + fcb[0]))));
    } else {
        if (g == 0) {
#pragma unroll
            for (int q = 0; q < QN; q++) {
                int d = dbase + q;
                if (d < 25) {
                    int f = head * 25 + d;
                    out[(size_t)w * OS + f] = (OT)(acc[q] * inv + bias[f]);
                }
            }
        }
    }
}

// ---------------------------------------------------------------------------
extern "C" void kernel_launch(void* const* d_in, const int* in_sizes, int n_in,
                              void* d_out, int out_size) {
    const float* feat = (const float*)d_in[0];
    const int*   src  = (const int*)d_in[1];
    const int*   dst  = (const int*)d_in[2];
    const float* W1   = (const float*)d_in[3];
    const float* al1  = (const float*)d_in[4];
    const float* ar1  = (const float*)d_in[5];
    const float* b1   = (const float*)d_in[6];
    const float* W2   = (const float*)d_in[7];
    const float* al2  = (const float*)d_in[8];
    const float* ar2  = (const float*)d_in[9];
    const float* b2   = (const float*)d_in[10];
    const float* W3   = (const float*)d_in[11];
    const float* al3  = (const float*)d_in[12];
    const float* ar3  = (const float*)d_in[13];
    const float* b3   = (const float*)d_in[14];
    const float* fcw  = (const float*)d_in[15];
    const float* fcb  = (const float*)d_in[16];
    float* out = (float*)d_out;

    int N = in_sizes[0] / 93;
    int E = in_sizes[1];
    int NB = (N + 1023) / 1024;
    int NP = ((N + 127) / 128) * 128;

    __half *xh2, *xh3, *hh;
    float *er;
    void* hraw;
    int *cnt, *rank, *loc, *bsum, *ssrc, *done;
    cudaGetSymbolAddress(&hraw, g_h);
    cudaGetSymbolAddress((void**)&xh2, g_xh2);
    cudaGetSymbolAddress((void**)&xh3, g_xh3);
    cudaGetSymbolAddress((void**)&er, g_er);
    cudaGetSymbolAddress((void**)&cnt, g_cnt);
    cudaGetSymbolAddress((void**)&rank, g_rank);
    cudaGetSymbolAddress((void**)&loc, g_loc);
    cudaGetSymbolAddress((void**)&bsum, g_bsum);
    cudaGetSymbolAddress((void**)&ssrc, g_ssrc);
    cudaGetSymbolAddress((void**)&done, g_done);
    hh = (__half*)hraw;

    int agrid = (N + 7) / 8;
    int hb = ((E + 3) / 4 + 255) / 256;
    const int GG = 592;                    // 4 blocks/SM gemm grid

    // launches: 0 hist(+wt), 1 scan1, 2 gemm1(+scatter), 3 agg1 (profiled),
    //           4 gemm2, 5 agg2, 6 gemm3, 7 agg3
    hist_kernel<<<hb + 8, 256>>>(dst, cnt, rank, E, hb,
                                 W1, al1, ar1, W2, al2, ar2, W3, al3, ar3);
    scan1_kernel<<<NB, 1024>>>(cnt, loc, bsum, done, N, NB);

    gemm_mma_kernel<96, 4, 2, WOFF1, AOFF1, true, true><<<GG + hb, 256>>>(
        feat, hh, er, NP / 64, N, GG,
        src, dst, loc, bsum, rank, ssrc, E);
    agg_kernel<4, 112, false, __half><<<agrid, 256>>>(
        hh, er, loc, bsum, ssrc, b1, xh2, fcw, fcb, N, E);

    gemm_mma_kernel<112, 2, 2, WOFF2, AOFF2, false, false><<<GG, 256>>>(
        xh2, hh, er, NP / 64, N, GG,
        nullptr, nullptr, nullptr, nullptr, nullptr, nullptr, 0);
    agg_kernel<2, 64, false, __half><<<agrid, 256>>>(
        hh, er, loc, bsum, ssrc, b2, xh3, fcw, fcb, N, E);

    gemm_mma_kernel<64, 1, 1, WOFF3, AOFF3, false, false><<<NP / 128, 256>>>(
        xh3, hh, er, NP / 128, N, NP / 128,
        nullptr, nullptr, nullptr, nullptr, nullptr, nullptr, 0);
    agg_kernel<1, 1, true, float><<<agrid, 256>>>(
        hh, er, loc, bsum, ssrc, b3, out, fcw, fcb, N, E);
}